// round 2
// baseline (speedup 1.0000x reference)
#include <cuda_runtime.h>

#define S_LEN    2048
#define L        50
#define LP       52        // padded row stride (16B-aligned, float4 friendly)
#define TILE     32
#define RROWS    (TILE + 6)
#define ITERS    3
#define NTHREADS 256

__global__ __launch_bounds__(NTHREADS) void mfvi_kernel(
    const float* __restrict__ unary,
    const float* __restrict__ mask,
    const float* __restrict__ Tg,
    const float* __restrict__ tstart,
    const float* __restrict__ tend,
    float* __restrict__ out)
{
    __shared__ alignas(16) float u [RROWS][LP];
    __shared__ alignas(16) float qA[RROWS][LP];
    __shared__ alignas(16) float qB[RROWS][LP];
    __shared__ alignas(16) float zr[LP];
    __shared__ float msm[RROWS];

    const int n    = blockIdx.y;
    const int p0   = blockIdx.x * TILE;
    const int base = p0 - 3;                 // smem row 0 <-> global position base
    const int tid  = threadIdx.x;
    const int grp  = tid >> 6;               // 4 groups of 64 threads (one row each)
    const int t    = tid & 63;               // output label slot (valid t < 50)
    const int warp = tid >> 5;
    const int lane = tid & 31;

    // ---- transition matrix into registers: column T[:,t] and row T[t,:] ----
    float Treg[LP], Ttreg[LP];
    #pragma unroll
    for (int a = 0; a < LP; a++) { Treg[a] = 0.f; Ttreg[a] = 0.f; }
    if (t < L) {
        #pragma unroll
        for (int a = 0; a < L; a++) Treg[a]  = Tg[a * L + t];   // for p(left) @ T
        #pragma unroll
        for (int b = 0; b < L; b++) Ttreg[b] = Tg[t * L + b];   // for p(right) @ T^T
    }
    const float tsr = (t < L) ? tstart[t] : 0.f;
    const float ter = (t < L) ? tend[t]   : 0.f;

    // ---- load masked unary into smem (with halo), init ping-pong buffers ----
    for (int idx = tid; idx < RROWS * LP; idx += NTHREADS) {
        int r = idx / LP, c = idx - r * LP;
        int g = base + r;
        float v = 0.f;
        if (c < L && g >= 0 && g < S_LEN)
            v = unary[((size_t)n * S_LEN + g) * L + c] * mask[(size_t)n * S_LEN + g];
        u [r][c] = v;
        qA[r][c] = v;      // q0 = unary * mask
        qB[r][c] = 0.f;    // pads (c>=50) must stay 0 forever
    }
    for (int r = tid; r < RROWS; r += NTHREADS) {
        int g = base + r;
        msm[r] = (g >= 0 && g < S_LEN) ? mask[(size_t)n * S_LEN + g] : 0.f;
    }
    for (int c = tid; c < LP; c += NTHREADS) zr[c] = 0.f;
    __syncthreads();

    float (*qsrc)[LP] = qA;
    float (*qdst)[LP] = qB;

    #pragma unroll
    for (int it = 0; it < ITERS; it++) {
        // -------- softmax in-place on qsrc over currently-valid rows --------
        {
            int glo = max(base + it, 0);
            int ghi = min(p0 + TILE + 3 - it, S_LEN);
            int rlo = glo - base, rhi = ghi - base;
            for (int r = rlo + warp; r < rhi; r += 8) {
                float v0 = qsrc[r][lane];
                float v1 = (lane < L - 32) ? qsrc[r][lane + 32] : -3.4e38f;
                float mx = fmaxf(v0, v1);
                #pragma unroll
                for (int o = 16; o > 0; o >>= 1)
                    mx = fmaxf(mx, __shfl_xor_sync(0xffffffffu, mx, o));
                float e0 = __expf(v0 - mx);
                float e1 = (lane < L - 32) ? __expf(v1 - mx) : 0.f;
                float s = e0 + e1;
                #pragma unroll
                for (int o = 16; o > 0; o >>= 1)
                    s += __shfl_xor_sync(0xffffffffu, s, o);
                float inv = __fdividef(1.f, s);
                qsrc[r][lane] = e0 * inv;
                if (lane < L - 32) qsrc[r][lane + 32] = e1 * inv;
            }
        }
        __syncthreads();

        // -------- messages + combine into qdst over shrunken range --------
        {
            int glo = max(base + it + 1, 0);
            int ghi = min(p0 + TILE + 3 - (it + 1), S_LEN);
            int rlo = glo - base, rhi = ghi - base;
            for (int r = rlo + grp; r < rhi; r += 4) {
                int g = base + r;
                const float* pm = (g == 0)         ? zr : qsrc[r - 1];
                const float* pp = (g == S_LEN - 1) ? zr : qsrc[r + 1];
                float aM0 = 0.f, aM1 = 0.f, aP0 = 0.f, aP1 = 0.f;
                #pragma unroll
                for (int a = 0; a < LP; a += 4) {
                    float4 m4 = *(const float4*)(pm + a);   // broadcast LDS.128
                    float4 p4 = *(const float4*)(pp + a);
                    aM0 = fmaf(m4.x, Treg[a + 0], aM0);
                    aM1 = fmaf(m4.y, Treg[a + 1], aM1);
                    aP0 = fmaf(p4.x, Ttreg[a + 0], aP0);
                    aP1 = fmaf(p4.y, Ttreg[a + 1], aP1);
                    aM0 = fmaf(m4.z, Treg[a + 2], aM0);
                    aM1 = fmaf(m4.w, Treg[a + 3], aM1);
                    aP0 = fmaf(p4.z, Ttreg[a + 2], aP0);
                    aP1 = fmaf(p4.w, Ttreg[a + 3], aP1);
                }
                // boundary semantics per reference:
                //   s_minus: pos 0 gets tstart (no left matvec); pos>=1 left matvec
                //   s_plus : pos<=S-2 right matvec; pos>=1 additionally gets tend
                float accM = aM0 + aM1 + ((g == 0) ? tsr : 0.f);
                float accP = aP0 + aP1 + ((g > 0) ? ter : 0.f);
                if (t < L)
                    qdst[r][t] = (u[r][t] + accM + accP) * msm[r];
            }
        }
        __syncthreads();

        float (*tmp)[LP] = qsrc; qsrc = qdst; qdst = tmp;
    }

    // ---- write final tile rows [p0, p0+TILE) (result lives in qsrc) ----
    for (int idx = tid; idx < TILE * L; idx += NTHREADS) {
        int r = idx / L, c = idx - r * L;
        out[((size_t)n * S_LEN + p0 + r) * L + c] = qsrc[3 + r][c];
    }
}

extern "C" void kernel_launch(void* const* d_in, const int* in_sizes, int n_in,
                              void* d_out, int out_size)
{
    const float* unary = (const float*)d_in[0];
    const float* mask  = (const float*)d_in[1];
    const float* T     = (const float*)d_in[2];
    const float* ts    = (const float*)d_in[3];
    const float* te    = (const float*)d_in[4];
    (void)n_in; (void)out_size;

    int NS = in_sizes[1];
    int N  = NS / S_LEN;
    dim3 grid(S_LEN / TILE, N);
    mfvi_kernel<<<grid, NTHREADS>>>(unary, mask, T, ts, te, (float*)d_out);
}

// round 3
// speedup vs baseline: 1.1714x; 1.1714x over previous
#include <cuda_runtime.h>

#define S_LEN    2048
#define L        50
#define LP       52        // padded row stride (16B aligned: 52 floats = 208B)
#define NPACK    26        // packed f32x2 pairs per row
#define TILE     64
#define RROWS    (TILE + 6)
#define ITERS    3
#define NTHREADS 256

typedef unsigned long long ull;

__device__ __forceinline__ ull pack2(float x, float y) {
    ull r; asm("mov.b64 %0, {%1, %2};" : "=l"(r) : "f"(x), "f"(y)); return r;
}
__device__ __forceinline__ void fma2(ull& d, ull a, ull b) {
    asm("fma.rn.f32x2 %0, %1, %2, %0;" : "+l"(d) : "l"(a), "l"(b));
}
__device__ __forceinline__ float sum2(ull v) {
    float lo, hi; asm("mov.b64 {%0, %1}, %2;" : "=f"(lo), "=f"(hi) : "l"(v));
    return lo + hi;
}

__global__ __launch_bounds__(NTHREADS, 2) void mfvi_kernel(
    const float* __restrict__ unary,
    const float* __restrict__ mask,
    const float* __restrict__ Tg,
    const float* __restrict__ tstart,
    const float* __restrict__ tend,
    float* __restrict__ out)
{
    __shared__ alignas(16) float u [RROWS][LP];
    __shared__ alignas(16) float qA[RROWS][LP];
    __shared__ alignas(16) float qB[RROWS][LP];
    __shared__ alignas(16) float zr[LP];
    __shared__ float msm[RROWS];

    const int n    = blockIdx.y;
    const int p0   = blockIdx.x * TILE;
    const int base = p0 - 3;                 // smem row 0 <-> global position base
    const int tid  = threadIdx.x;
    const int grp  = tid >> 6;               // 4 groups of 64 threads
    const int t    = tid & 63;               // label slot (valid t < 50)
    const int warp = tid >> 5;
    const int lane = tid & 31;

    // ---- transition matrix into registers, packed pairwise along sum dim ----
    ull Tp[NPACK], Ttp[NPACK];               // Tp[i]=(T[2i][t],T[2i+1][t]) ; Ttp[i]=(T[t][2i],T[t][2i+1])
    #pragma unroll
    for (int i = 0; i < NPACK; i++) { Tp[i] = 0ull; Ttp[i] = 0ull; }
    if (t < L) {
        #pragma unroll
        for (int i = 0; i < NPACK; i++) {
            int a0 = 2 * i, a1 = 2 * i + 1;
            float c0 = Tg[a0 * L + t];
            float c1 = (a1 < L) ? Tg[a1 * L + t] : 0.f;
            Tp[i] = pack2(c0, c1);
            float r0 = Tg[t * L + a0];
            float r1 = (a1 < L) ? Tg[t * L + a1] : 0.f;
            Ttp[i] = pack2(r0, r1);
        }
    }
    const float tsr = (t < L) ? tstart[t] : 0.f;
    const float ter = (t < L) ? tend[t]   : 0.f;

    // ---- load masked unary into smem (with halo), init ping-pong buffers ----
    for (int idx = tid; idx < RROWS * LP; idx += NTHREADS) {
        int r = idx / LP, c = idx - r * LP;
        int g = base + r;
        float v = 0.f;
        if (c < L && g >= 0 && g < S_LEN)
            v = unary[((size_t)n * S_LEN + g) * L + c] * mask[(size_t)n * S_LEN + g];
        u [r][c] = v;
        qA[r][c] = v;      // q0 = unary * mask
        qB[r][c] = 0.f;    // pads (c>=50) must stay 0 forever
    }
    for (int r = tid; r < RROWS; r += NTHREADS) {
        int g = base + r;
        msm[r] = (g >= 0 && g < S_LEN) ? mask[(size_t)n * S_LEN + g] : 0.f;
    }
    for (int c = tid; c < LP; c += NTHREADS) zr[c] = 0.f;
    __syncthreads();

    float (*qsrc)[LP] = qA;
    float (*qdst)[LP] = qB;

    #pragma unroll
    for (int it = 0; it < ITERS; it++) {
        // -------- softmax in-place on qsrc over currently-valid rows --------
        {
            int glo = max(base + it, 0);
            int ghi = min(p0 + TILE + 3 - it, S_LEN);
            int rlo = glo - base, rhi = ghi - base;
            for (int r = rlo + warp; r < rhi; r += 8) {
                float v0 = qsrc[r][lane];
                float v1 = (lane < L - 32) ? qsrc[r][lane + 32] : -3.4e38f;
                float mx = fmaxf(v0, v1);
                #pragma unroll
                for (int o = 16; o > 0; o >>= 1)
                    mx = fmaxf(mx, __shfl_xor_sync(0xffffffffu, mx, o));
                float e0 = __expf(v0 - mx);
                float e1 = (lane < L - 32) ? __expf(v1 - mx) : 0.f;
                float s = e0 + e1;
                #pragma unroll
                for (int o = 16; o > 0; o >>= 1)
                    s += __shfl_xor_sync(0xffffffffu, s, o);
                float inv = __fdividef(1.f, s);
                qsrc[r][lane] = e0 * inv;
                if (lane < L - 32) qsrc[r][lane + 32] = e1 * inv;
            }
        }
        __syncthreads();

        // -------- messages + combine into qdst, two dest rows per group-iter --------
        // dest rows d0=r, d1=r+2 share source row r+1 (saves 1 of 4 row loads)
        {
            int glo = max(base + it + 1, 0);
            int ghi = min(p0 + TILE + 3 - (it + 1), S_LEN);
            int rlo = glo - base, rhi = ghi - base;
            // chunk of 8 rows -> groups take offsets {0,1,4,5}, pairs (+0,+2)
            int off = (grp & 1) + ((grp >> 1) << 2);
            for (int c8 = rlo; c8 < rhi; c8 += 8) {
                int d0 = c8 + off;
                if (d0 >= rhi) break;
                int d1 = d0 + 2;
                bool d1ok = (d1 < rhi);
                int g0 = base + d0;

                const float* pm = (g0 == 0)                     ? zr : qsrc[d0 - 1];
                const float* pc = (g0 == S_LEN - 1)             ? zr : qsrc[d0 + 1];
                const float* pp = (!d1ok || g0 + 2 == S_LEN - 1)? zr : qsrc[d1 + 1];

                ull aM0 = 0ull, aP0 = 0ull, aM1 = 0ull, aP1 = 0ull;
                #pragma unroll
                for (int i = 0; i < NPACK; i += 2) {
                    ulonglong2 m2 = *(const ulonglong2*)(pm + 2 * i);
                    ulonglong2 c2 = *(const ulonglong2*)(pc + 2 * i);
                    ulonglong2 p2 = *(const ulonglong2*)(pp + 2 * i);
                    fma2(aM0, m2.x, Tp [i]);  fma2(aM0, m2.y, Tp [i + 1]);
                    fma2(aP0, c2.x, Ttp[i]);  fma2(aP0, c2.y, Ttp[i + 1]);
                    fma2(aM1, c2.x, Tp [i]);  fma2(aM1, c2.y, Tp [i + 1]);
                    fma2(aP1, p2.x, Ttp[i]);  fma2(aP1, p2.y, Ttp[i + 1]);
                }
                if (t < L) {
                    // boundary semantics (reference): pos 0 gets tstart instead of
                    // left matvec; every pos>=1 gets tend added to s_plus.
                    float accM0 = sum2(aM0) + ((g0 == 0) ? tsr : 0.f);
                    float accP0 = sum2(aP0) + ((g0 > 0) ? ter : 0.f);
                    qdst[d0][t] = (u[d0][t] + accM0 + accP0) * msm[d0];
                    if (d1ok) {
                        // g1 = g0+2 >= 2 always: left matvec + tend, no tstart
                        float accM1 = sum2(aM1);
                        float accP1 = sum2(aP1) + ter;
                        qdst[d1][t] = (u[d1][t] + accM1 + accP1) * msm[d1];
                    }
                }
            }
        }
        __syncthreads();

        float (*tmp)[LP] = qsrc; qsrc = qdst; qdst = tmp;
    }

    // ---- write final tile rows [p0, p0+TILE) (result lives in qsrc) ----
    for (int idx = tid; idx < TILE * L; idx += NTHREADS) {
        int r = idx / L, c = idx - r * L;
        out[((size_t)n * S_LEN + p0 + r) * L + c] = qsrc[3 + r][c];
    }
}

extern "C" void kernel_launch(void* const* d_in, const int* in_sizes, int n_in,
                              void* d_out, int out_size)
{
    const float* unary = (const float*)d_in[0];
    const float* mask  = (const float*)d_in[1];
    const float* T     = (const float*)d_in[2];
    const float* ts    = (const float*)d_in[3];
    const float* te    = (const float*)d_in[4];
    (void)n_in; (void)out_size;

    int NS = in_sizes[1];
    int N  = NS / S_LEN;
    dim3 grid(S_LEN / TILE, N);
    mfvi_kernel<<<grid, NTHREADS>>>(unary, mask, T, ts, te, (float*)d_out);
}